// round 2
// baseline (speedup 1.0000x reference)
#include <cuda_runtime.h>

// Skip-gram negative-sampling loss (PennSkipGramModel), single fused kernel.
// Inputs (metadata order):
//   0: u_l_weight  [100000*128] f32
//   1: u_r_weight  [100000*128] f32
//   2: v_l_weight  [100000*128] f32
//   3: v_r_weight  [100000*128] f32
//   4: pos_u       [B]     i32
//   5: pos_v_l     [B]     i32
//   6: pos_v_r     [B]     i32
//   7: neg_v_l     [B*K]   i32
//   8: neg_v_r     [B*K]   i32
// Output: scalar f32 mean loss.

#define HALF 128
#define KNEG 5
#define BLOCK_THREADS 256
#define WARPS_PER_BLOCK (BLOCK_THREADS / 32)
#define MAX_PARTIALS 16384

__device__ float g_partials[MAX_PARTIALS];
__device__ unsigned int g_ticket = 0;   // reset by the last block each call

__device__ __forceinline__ float warp_reduce_sum(float v) {
    v += __shfl_xor_sync(0xffffffffu, v, 16);
    v += __shfl_xor_sync(0xffffffffu, v, 8);
    v += __shfl_xor_sync(0xffffffffu, v, 4);
    v += __shfl_xor_sync(0xffffffffu, v, 2);
    v += __shfl_xor_sync(0xffffffffu, v, 1);
    return v;
}

// softplus(x) = log(1 + exp(x)); inputs pre-clipped to [-10, 10] so
// exp(x) <= 22027 -> no overflow, log1pf keeps accuracy near 0.
__device__ __forceinline__ float softplus_clipped(float x) {
    return log1pf(expf(x));
}

__device__ __forceinline__ float clip10(float x) {
    return fminf(fmaxf(x, -10.0f), 10.0f);
}

__device__ __forceinline__ float dot4(float4 a, float4 b) {
    return fmaf(a.x, b.x, fmaf(a.y, b.y, fmaf(a.z, b.z, a.w * b.w)));
}

__global__ void __launch_bounds__(BLOCK_THREADS)
skipgram_loss_fused_kernel(
    const float* __restrict__ u_l, const float* __restrict__ u_r,
    const float* __restrict__ v_l, const float* __restrict__ v_r,
    const int* __restrict__ pos_u,
    const int* __restrict__ pos_v_l, const int* __restrict__ pos_v_r,
    const int* __restrict__ neg_v_l, const int* __restrict__ neg_v_r,
    float* __restrict__ out,
    int batch, float inv_b)
{
    const int lane = threadIdx.x & 31;
    const int warp_in_block = threadIdx.x >> 5;
    const int b = blockIdx.x * WARPS_PER_BLOCK + warp_in_block;

    float acc = 0.0f;

    if (b < batch) {
        // ---- gather all indices first (lane-uniform broadcast loads) ----
        const int iu  = pos_u[b];
        const int ipl = pos_v_l[b];
        const int ipr = pos_v_r[b];
        int inl[KNEG], inr[KNEG];
#pragma unroll
        for (int k = 0; k < KNEG; k++) inl[k] = neg_v_l[b * KNEG + k];
#pragma unroll
        for (int k = 0; k < KNEG; k++) inr[k] = neg_v_r[b * KNEG + k];

        const int off = lane * 4;

        // ---- front-batch all 14 row loads (float4 per lane) for MLP ----
        const float4 ul  = *(const float4*)(u_l + (size_t)iu  * HALF + off);
        const float4 ur  = *(const float4*)(u_r + (size_t)iu  * HALF + off);
        const float4 vpl = *(const float4*)(v_l + (size_t)ipl * HALF + off);
        const float4 vpr = *(const float4*)(v_r + (size_t)ipr * HALF + off);
        float4 vnl[KNEG], vnr[KNEG];
#pragma unroll
        for (int k = 0; k < KNEG; k++)
            vnl[k] = *(const float4*)(v_l + (size_t)inl[k] * HALF + off);
#pragma unroll
        for (int k = 0; k < KNEG; k++)
            vnr[k] = *(const float4*)(v_r + (size_t)inr[k] * HALF + off);

        // ---- positive scores: -logsigmoid(d) = softplus(-d) ----
        float dl = warp_reduce_sum(dot4(ul, vpl));
        float dr = warp_reduce_sum(dot4(ur, vpr));
        acc += softplus_clipped(-clip10(dl));
        acc += softplus_clipped(-clip10(dr));

        // ---- negative scores: -logsigmoid(-d) = softplus(d) ----
#pragma unroll
        for (int k = 0; k < KNEG; k++) {
            float d = warp_reduce_sum(dot4(ul, vnl[k]));
            acc += softplus_clipped(clip10(d));
        }
#pragma unroll
        for (int k = 0; k < KNEG; k++) {
            float d = warp_reduce_sum(dot4(ur, vnr[k]));
            acc += softplus_clipped(clip10(d));
        }
    }

    // ---- block reduce (all lanes of a warp hold identical acc) ----
    __shared__ float s_warp[WARPS_PER_BLOCK];
    __shared__ bool s_is_last;
    if (lane == 0) s_warp[warp_in_block] = acc;
    __syncthreads();

    if (threadIdx.x == 0) {
        float v = 0.0f;
#pragma unroll
        for (int w = 0; w < WARPS_PER_BLOCK; w++) v += s_warp[w];
        g_partials[blockIdx.x] = v;
        // make the partial visible before taking a ticket
        __threadfence();
        unsigned int t = atomicAdd(&g_ticket, 1u);
        s_is_last = (t == gridDim.x - 1);
    }
    __syncthreads();

    // ---- last block to finish performs the deterministic final reduce ----
    if (s_is_last) {
        const int nparts = gridDim.x;
        float a = 0.0f;
        // strided loop -> 32 independent loads per thread, high MLP
        for (int i = threadIdx.x; i < nparts; i += BLOCK_THREADS)
            a += g_partials[i];

        __shared__ float s_red[BLOCK_THREADS];
        s_red[threadIdx.x] = a;
        __syncthreads();
#pragma unroll
        for (int st = BLOCK_THREADS / 2; st > 0; st >>= 1) {
            if (threadIdx.x < st) s_red[threadIdx.x] += s_red[threadIdx.x + st];
            __syncthreads();
        }
        if (threadIdx.x == 0) {
            out[0] = s_red[0] * inv_b;
            g_ticket = 0;  // reset for next graph replay
        }
    }
}

extern "C" void kernel_launch(void* const* d_in, const int* in_sizes, int n_in,
                              void* d_out, int out_size)
{
    const float* u_l = (const float*)d_in[0];
    const float* u_r = (const float*)d_in[1];
    const float* v_l = (const float*)d_in[2];
    const float* v_r = (const float*)d_in[3];
    const int* pos_u   = (const int*)d_in[4];
    const int* pos_v_l = (const int*)d_in[5];
    const int* pos_v_r = (const int*)d_in[6];
    const int* neg_v_l = (const int*)d_in[7];
    const int* neg_v_r = (const int*)d_in[8];

    const int batch = in_sizes[4];
    const int nblocks = (batch + WARPS_PER_BLOCK - 1) / WARPS_PER_BLOCK;
    // nblocks = 8192 for B=65536; MAX_PARTIALS=16384 headroom.

    skipgram_loss_fused_kernel<<<nblocks, BLOCK_THREADS>>>(
        u_l, u_r, v_l, v_r, pos_u, pos_v_l, pos_v_r, neg_v_l, neg_v_r,
        (float*)d_out, batch, 1.0f / (float)batch);
}

// round 3
// speedup vs baseline: 1.2121x; 1.2121x over previous
#include <cuda_runtime.h>

// Skip-gram negative-sampling loss (PennSkipGramModel), single kernel,
// fence-free deterministic reduction via packed 64-bit atomic.
//
// Inputs (metadata order):
//   0: u_l_weight  [100000*128] f32
//   1: u_r_weight  [100000*128] f32
//   2: v_l_weight  [100000*128] f32
//   3: v_r_weight  [100000*128] f32
//   4: pos_u       [B]     i32
//   5: pos_v_l     [B]     i32
//   6: pos_v_r     [B]     i32
//   7: neg_v_l     [B*K]   i32
//   8: neg_v_r     [B*K]   i32
// Output: scalar f32 mean loss.

#define HALF 128
#define KNEG 5
#define BLOCK_THREADS 256
#define WARPS_PER_BLOCK (BLOCK_THREADS / 32)

// Packed accumulator: bits [0:42) fixed-point sum (scale 2^18),
// bits [42:...) block arrival count. Max block sum = 8 elem * 12 * 10.0001
// = 960.01 -> *2^18 = 2.5e8; * 8192 blocks = 2.06e12 < 2^41. Count max
// 8192 = 2^13 at bit 42 -> bit 55. No overflow.
#define FP_SCALE 262144.0   // 2^18
#define COUNT_SHIFT 42
#define SUM_MASK ((1ULL << COUNT_SHIFT) - 1ULL)

__device__ unsigned long long g_accum = 0ULL;

__device__ __forceinline__ float warp_reduce_sum(float v) {
    v += __shfl_xor_sync(0xffffffffu, v, 16);
    v += __shfl_xor_sync(0xffffffffu, v, 8);
    v += __shfl_xor_sync(0xffffffffu, v, 4);
    v += __shfl_xor_sync(0xffffffffu, v, 2);
    v += __shfl_xor_sync(0xffffffffu, v, 1);
    return v;
}

// softplus(x) = log(1 + exp(x)), fast-math. Inputs pre-clipped to [-10,10]
// so exp(x) <= 22027: no overflow. MUFU-based, ~5 SASS instrs.
__device__ __forceinline__ float softplus_fast(float x) {
    return __logf(1.0f + __expf(x));
}

__device__ __forceinline__ float clip10(float x) {
    return fminf(fmaxf(x, -10.0f), 10.0f);
}

__device__ __forceinline__ float dot4(float4 a, float4 b) {
    return fmaf(a.x, b.x, fmaf(a.y, b.y, fmaf(a.z, b.z, a.w * b.w)));
}

__global__ void __launch_bounds__(BLOCK_THREADS)
skipgram_loss_kernel(
    const float* __restrict__ u_l, const float* __restrict__ u_r,
    const float* __restrict__ v_l, const float* __restrict__ v_r,
    const int* __restrict__ pos_u,
    const int* __restrict__ pos_v_l, const int* __restrict__ pos_v_r,
    const int* __restrict__ neg_v_l, const int* __restrict__ neg_v_r,
    float* __restrict__ out,
    int batch)
{
    const int lane = threadIdx.x & 31;
    const int warp_in_block = threadIdx.x >> 5;
    const int b = blockIdx.x * WARPS_PER_BLOCK + warp_in_block;

    float acc = 0.0f;

    if (b < batch) {
        // ---- gather all indices first (lane-uniform broadcast loads) ----
        const int iu  = pos_u[b];
        const int ipl = pos_v_l[b];
        const int ipr = pos_v_r[b];
        int inl[KNEG], inr[KNEG];
#pragma unroll
        for (int k = 0; k < KNEG; k++) inl[k] = neg_v_l[b * KNEG + k];
#pragma unroll
        for (int k = 0; k < KNEG; k++) inr[k] = neg_v_r[b * KNEG + k];

        const int off = lane * 4;

        // ---- front-batch all 14 row loads (float4 per lane) for MLP ----
        const float4 ul  = *(const float4*)(u_l + (size_t)iu  * HALF + off);
        const float4 ur  = *(const float4*)(u_r + (size_t)iu  * HALF + off);
        const float4 vpl = *(const float4*)(v_l + (size_t)ipl * HALF + off);
        const float4 vpr = *(const float4*)(v_r + (size_t)ipr * HALF + off);
        float4 vnl[KNEG], vnr[KNEG];
#pragma unroll
        for (int k = 0; k < KNEG; k++)
            vnl[k] = *(const float4*)(v_l + (size_t)inl[k] * HALF + off);
#pragma unroll
        for (int k = 0; k < KNEG; k++)
            vnr[k] = *(const float4*)(v_r + (size_t)inr[k] * HALF + off);

        // ---- positive scores: -logsigmoid(d) = softplus(-d) ----
        float dl = warp_reduce_sum(dot4(ul, vpl));
        float dr = warp_reduce_sum(dot4(ur, vpr));
        acc += softplus_fast(-clip10(dl));
        acc += softplus_fast(-clip10(dr));

        // ---- negative scores: -logsigmoid(-d) = softplus(d) ----
#pragma unroll
        for (int k = 0; k < KNEG; k++) {
            float d = warp_reduce_sum(dot4(ul, vnl[k]));
            acc += softplus_fast(clip10(d));
        }
#pragma unroll
        for (int k = 0; k < KNEG; k++) {
            float d = warp_reduce_sum(dot4(ur, vnr[k]));
            acc += softplus_fast(clip10(d));
        }
    }

    // ---- block reduce (all lanes of a warp hold identical acc) ----
    __shared__ float s_warp[WARPS_PER_BLOCK];
    if (lane == 0) s_warp[warp_in_block] = acc;
    __syncthreads();

    if (threadIdx.x == 0) {
        float v = 0.0f;
#pragma unroll
        for (int w = 0; w < WARPS_PER_BLOCK; w++) v += s_warp[w];

        // Fixed-point contribution (order-independent -> deterministic),
        // packed with a count increment. No threadfence needed: the atomic
        // return value carries the running total.
        unsigned long long fx =
            (unsigned long long)((double)v * FP_SCALE + 0.5);
        unsigned long long old =
            atomicAdd(&g_accum, fx + (1ULL << COUNT_SHIFT));

        if ((old >> COUNT_SHIFT) == (unsigned long long)(gridDim.x - 1)) {
            // I'm the last block: old holds everyone else's sum.
            unsigned long long total = (old & SUM_MASK) + fx;
            double mean = (double)total / FP_SCALE / (double)batch;
            out[0] = (float)mean;
            // reset for the next graph replay (all peers already arrived)
            atomicExch(&g_accum, 0ULL);
        }
    }
}

extern "C" void kernel_launch(void* const* d_in, const int* in_sizes, int n_in,
                              void* d_out, int out_size)
{
    const float* u_l = (const float*)d_in[0];
    const float* u_r = (const float*)d_in[1];
    const float* v_l = (const float*)d_in[2];
    const float* v_r = (const float*)d_in[3];
    const int* pos_u   = (const int*)d_in[4];
    const int* pos_v_l = (const int*)d_in[5];
    const int* pos_v_r = (const int*)d_in[6];
    const int* neg_v_l = (const int*)d_in[7];
    const int* neg_v_r = (const int*)d_in[8];

    const int batch = in_sizes[4];
    const int nblocks = (batch + WARPS_PER_BLOCK - 1) / WARPS_PER_BLOCK;

    skipgram_loss_kernel<<<nblocks, BLOCK_THREADS>>>(
        u_l, u_r, v_l, v_r, pos_u, pos_v_l, pos_v_r, neg_v_l, neg_v_r,
        (float*)d_out, batch);
}

// round 4
// speedup vs baseline: 1.2175x; 1.0044x over previous
#include <cuda_runtime.h>

// Skip-gram negative-sampling loss (PennSkipGramModel), single kernel,
// fence-free deterministic reduction via packed 64-bit atomic.
// R4: phased row loads + __launch_bounds__ to cut regs 64 -> ~50 and raise
// occupancy (latency-bound per R3 ncu: DRAM 50%, issue 38%, occ 44%).
//
// Inputs (metadata order):
//   0: u_l_weight  [100000*128] f32
//   1: u_r_weight  [100000*128] f32
//   2: v_l_weight  [100000*128] f32
//   3: v_r_weight  [100000*128] f32
//   4: pos_u       [B]     i32
//   5: pos_v_l     [B]     i32
//   6: pos_v_r     [B]     i32
//   7: neg_v_l     [B*K]   i32
//   8: neg_v_r     [B*K]   i32
// Output: scalar f32 mean loss.

#define HALF 128
#define KNEG 5
#define BLOCK_THREADS 256
#define WARPS_PER_BLOCK (BLOCK_THREADS / 32)

// Packed accumulator: bits [0:42) fixed-point sum (scale 2^18),
// bits [42:...) block arrival count. Max block sum ~960 -> *2^18 = 2.5e8;
// * 8192 blocks = 2.06e12 < 2^41. Count 8192 at bit 42 -> bit 55. Safe.
#define FP_SCALE 262144.0   // 2^18
#define COUNT_SHIFT 42
#define SUM_MASK ((1ULL << COUNT_SHIFT) - 1ULL)

__device__ unsigned long long g_accum = 0ULL;

__device__ __forceinline__ float warp_reduce_sum(float v) {
    v += __shfl_xor_sync(0xffffffffu, v, 16);
    v += __shfl_xor_sync(0xffffffffu, v, 8);
    v += __shfl_xor_sync(0xffffffffu, v, 4);
    v += __shfl_xor_sync(0xffffffffu, v, 2);
    v += __shfl_xor_sync(0xffffffffu, v, 1);
    return v;
}

// softplus(x) = log(1 + exp(x)), fast-math (MUFU). Inputs pre-clipped to
// [-10,10] so exp(x) <= 22027: no overflow.
__device__ __forceinline__ float softplus_fast(float x) {
    return __logf(1.0f + __expf(x));
}

__device__ __forceinline__ float clip10(float x) {
    return fminf(fmaxf(x, -10.0f), 10.0f);
}

__device__ __forceinline__ float dot4(float4 a, float4 b) {
    return fmaf(a.x, b.x, fmaf(a.y, b.y, fmaf(a.z, b.z, a.w * b.w)));
}

__global__ void __launch_bounds__(BLOCK_THREADS, 5)
skipgram_loss_kernel(
    const float* __restrict__ u_l, const float* __restrict__ u_r,
    const float* __restrict__ v_l, const float* __restrict__ v_r,
    const int* __restrict__ pos_u,
    const int* __restrict__ pos_v_l, const int* __restrict__ pos_v_r,
    const int* __restrict__ neg_v_l, const int* __restrict__ neg_v_r,
    float* __restrict__ out,
    int batch)
{
    const int lane = threadIdx.x & 31;
    const int warp_in_block = threadIdx.x >> 5;
    const int b = blockIdx.x * WARPS_PER_BLOCK + warp_in_block;

    float acc = 0.0f;

    if (b < batch) {
        const int off = lane * 4;

        // ---- indices (lane-uniform broadcast loads) ----
        const int iu  = pos_u[b];
        const int ipl = pos_v_l[b];
        const int ipr = pos_v_r[b];
        int inl[KNEG];
#pragma unroll
        for (int k = 0; k < KNEG; k++) inl[k] = neg_v_l[b * KNEG + k];

        // ---- phase A: 9 front-batched row loads (u, pos, neg-left) ----
        const float4 ul  = *(const float4*)(u_l + (size_t)iu  * HALF + off);
        const float4 ur  = *(const float4*)(u_r + (size_t)iu  * HALF + off);
        const float4 vpl = *(const float4*)(v_l + (size_t)ipl * HALF + off);
        const float4 vpr = *(const float4*)(v_r + (size_t)ipr * HALF + off);
        float4 vnl[KNEG];
#pragma unroll
        for (int k = 0; k < KNEG; k++)
            vnl[k] = *(const float4*)(v_l + (size_t)inl[k] * HALF + off);

        // lane-partial dots consume vnl -> frees 20 regs
        float pl[KNEG];
#pragma unroll
        for (int k = 0; k < KNEG; k++) pl[k] = dot4(ul, vnl[k]);
        float dpl = dot4(ul, vpl);
        float dpr = dot4(ur, vpr);

        // ---- phase B: issue neg-right loads early to overlap the
        //      reductions / softplus of the left side ----
        int inr[KNEG];
#pragma unroll
        for (int k = 0; k < KNEG; k++) inr[k] = neg_v_r[b * KNEG + k];
        float4 vnr[KNEG];
#pragma unroll
        for (int k = 0; k < KNEG; k++)
            vnr[k] = *(const float4*)(v_r + (size_t)inr[k] * HALF + off);

        // ---- reduce + activate left side while vnr loads are in flight ----
        acc += softplus_fast(-clip10(warp_reduce_sum(dpl)));
        acc += softplus_fast(-clip10(warp_reduce_sum(dpr)));
#pragma unroll
        for (int k = 0; k < KNEG; k++)
            acc += softplus_fast(clip10(warp_reduce_sum(pl[k])));

        // ---- right-side negatives ----
#pragma unroll
        for (int k = 0; k < KNEG; k++) {
            float d = warp_reduce_sum(dot4(ur, vnr[k]));
            acc += softplus_fast(clip10(d));
        }
    }

    // ---- block reduce (all lanes of a warp hold identical acc) ----
    __shared__ float s_warp[WARPS_PER_BLOCK];
    if (lane == 0) s_warp[warp_in_block] = acc;
    __syncthreads();

    if (threadIdx.x == 0) {
        float v = 0.0f;
#pragma unroll
        for (int w = 0; w < WARPS_PER_BLOCK; w++) v += s_warp[w];

        // Fixed-point contribution (order-independent -> deterministic),
        // packed with an arrival count. The atomic return value carries the
        // running total: no threadfence (avoids CCTL.IVALL L1 flush).
        unsigned long long fx =
            (unsigned long long)((double)v * FP_SCALE + 0.5);
        unsigned long long old =
            atomicAdd(&g_accum, fx + (1ULL << COUNT_SHIFT));

        if ((old >> COUNT_SHIFT) == (unsigned long long)(gridDim.x - 1)) {
            unsigned long long total = (old & SUM_MASK) + fx;
            double mean = (double)total / FP_SCALE / (double)batch;
            out[0] = (float)mean;
            atomicExch(&g_accum, 0ULL);  // reset for next graph replay
        }
    }
}

extern "C" void kernel_launch(void* const* d_in, const int* in_sizes, int n_in,
                              void* d_out, int out_size)
{
    const float* u_l = (const float*)d_in[0];
    const float* u_r = (const float*)d_in[1];
    const float* v_l = (const float*)d_in[2];
    const float* v_r = (const float*)d_in[3];
    const int* pos_u   = (const int*)d_in[4];
    const int* pos_v_l = (const int*)d_in[5];
    const int* pos_v_r = (const int*)d_in[6];
    const int* neg_v_l = (const int*)d_in[7];
    const int* neg_v_r = (const int*)d_in[8];

    const int batch = in_sizes[4];
    const int nblocks = (batch + WARPS_PER_BLOCK - 1) / WARPS_PER_BLOCK;

    skipgram_loss_kernel<<<nblocks, BLOCK_THREADS>>>(
        u_l, u_r, v_l, v_r, pos_u, pos_v_l, pos_v_r, neg_v_l, neg_v_r,
        (float*)d_out, batch);
}

// round 5
// speedup vs baseline: 1.2717x; 1.0445x over previous
#include <cuda_runtime.h>

// Skip-gram negative-sampling loss (PennSkipGramModel), single kernel.
// R5: phase-split grid — blocks [0,nb) process LEFT terms (u_l/v_l only,
// 74.8MB unique working set < 126MB L2), blocks [nb,2nb) process RIGHT
// terms. Each phase's working set is L2-resident -> v-row reuse (~4x) hits
// L2 instead of DRAM. Fence-free deterministic packed-atomic reduction.
//
// Inputs (metadata order):
//   0: u_l_weight  [100000*128] f32     4: pos_u    [B]   i32
//   1: u_r_weight  [100000*128] f32     5: pos_v_l  [B]   i32
//   2: v_l_weight  [100000*128] f32     6: pos_v_r  [B]   i32
//   3: v_r_weight  [100000*128] f32     7: neg_v_l  [B*K] i32
//                                       8: neg_v_r  [B*K] i32
// Output: scalar f32 mean loss.

#define HALF 128
#define KNEG 5
#define BLOCK_THREADS 256
#define WARPS_PER_BLOCK (BLOCK_THREADS / 32)

// Packed accumulator: bits [0:42) fixed-point sum (scale 2^18), bits [42:..)
// block arrival count. Per-block max sum = 8 elems * 6 terms * 10.0001 ~ 480
// -> *2^18 = 1.26e8; * 16384 blocks = 2.06e12 < 2^41. Count 16384 fits. Safe.
#define FP_SCALE 262144.0   // 2^18
#define COUNT_SHIFT 42
#define SUM_MASK ((1ULL << COUNT_SHIFT) - 1ULL)

__device__ unsigned long long g_accum = 0ULL;

__device__ __forceinline__ float warp_reduce_sum(float v) {
    v += __shfl_xor_sync(0xffffffffu, v, 16);
    v += __shfl_xor_sync(0xffffffffu, v, 8);
    v += __shfl_xor_sync(0xffffffffu, v, 4);
    v += __shfl_xor_sync(0xffffffffu, v, 2);
    v += __shfl_xor_sync(0xffffffffu, v, 1);
    return v;
}

// softplus(x) = log(1 + exp(x)), fast-math (MUFU). Inputs pre-clipped to
// [-10,10] so exp(x) <= 22027: no overflow.
__device__ __forceinline__ float softplus_fast(float x) {
    return __logf(1.0f + __expf(x));
}

__device__ __forceinline__ float clip10(float x) {
    return fminf(fmaxf(x, -10.0f), 10.0f);
}

__device__ __forceinline__ float dot4(float4 a, float4 b) {
    return fmaf(a.x, b.x, fmaf(a.y, b.y, fmaf(a.z, b.z, a.w * b.w)));
}

__global__ void __launch_bounds__(BLOCK_THREADS, 5)
skipgram_loss_kernel(
    const float* __restrict__ u_l, const float* __restrict__ u_r,
    const float* __restrict__ v_l, const float* __restrict__ v_r,
    const int* __restrict__ pos_u,
    const int* __restrict__ pos_v_l, const int* __restrict__ pos_v_r,
    const int* __restrict__ neg_v_l, const int* __restrict__ neg_v_r,
    float* __restrict__ out,
    int batch)
{
    const int lane = threadIdx.x & 31;
    const int warp_in_block = threadIdx.x >> 5;

    // Phase split: first half of grid = left side, second half = right side.
    const int nb = gridDim.x >> 1;
    const bool right = (blockIdx.x >= (unsigned)nb);
    const int blk = right ? (blockIdx.x - nb) : blockIdx.x;
    const int b = blk * WARPS_PER_BLOCK + warp_in_block;

    const float* __restrict__ U    = right ? u_r : u_l;
    const float* __restrict__ V    = right ? v_r : v_l;
    const int*   __restrict__ posv = right ? pos_v_r : pos_v_l;
    const int*   __restrict__ negv = right ? neg_v_r : neg_v_l;

    float acc = 0.0f;

    if (b < batch) {
        const int off = lane * 4;

        // ---- indices (lane-uniform broadcast loads) ----
        const int iu = pos_u[b];
        const int ip = posv[b];
        int in[KNEG];
#pragma unroll
        for (int k = 0; k < KNEG; k++) in[k] = negv[b * KNEG + k];

        // ---- front-batch all 7 row loads (float4 per lane) ----
        const float4 uu = *(const float4*)(U + (size_t)iu * HALF + off);
        const float4 vp = *(const float4*)(V + (size_t)ip * HALF + off);
        float4 vn[KNEG];
#pragma unroll
        for (int k = 0; k < KNEG; k++)
            vn[k] = *(const float4*)(V + (size_t)in[k] * HALF + off);

        // ---- lane-partial dots ----
        float dp = dot4(uu, vp);
        float dn[KNEG];
#pragma unroll
        for (int k = 0; k < KNEG; k++) dn[k] = dot4(uu, vn[k]);

        // ---- reduce + activations ----
        // positive: -logsigmoid(d) = softplus(-d); negative: softplus(d)
        acc += softplus_fast(-clip10(warp_reduce_sum(dp)));
#pragma unroll
        for (int k = 0; k < KNEG; k++)
            acc += softplus_fast(clip10(warp_reduce_sum(dn[k])));
    }

    // ---- block reduce (all lanes of a warp hold identical acc) ----
    __shared__ float s_warp[WARPS_PER_BLOCK];
    if (lane == 0) s_warp[warp_in_block] = acc;
    __syncthreads();

    if (threadIdx.x == 0) {
        float v = 0.0f;
#pragma unroll
        for (int w = 0; w < WARPS_PER_BLOCK; w++) v += s_warp[w];

        // Fixed-point contribution (order-independent -> deterministic),
        // packed with an arrival count; atomic return value carries the
        // running total (no threadfence -> no CCTL.IVALL L1 flush).
        unsigned long long fx =
            (unsigned long long)((double)v * FP_SCALE + 0.5);
        unsigned long long old =
            atomicAdd(&g_accum, fx + (1ULL << COUNT_SHIFT));

        if ((old >> COUNT_SHIFT) == (unsigned long long)(gridDim.x - 1)) {
            unsigned long long total = (old & SUM_MASK) + fx;
            double mean = (double)total / FP_SCALE / (double)batch;
            out[0] = (float)mean;
            atomicExch(&g_accum, 0ULL);  // reset for next graph replay
        }
    }
}

extern "C" void kernel_launch(void* const* d_in, const int* in_sizes, int n_in,
                              void* d_out, int out_size)
{
    const float* u_l = (const float*)d_in[0];
    const float* u_r = (const float*)d_in[1];
    const float* v_l = (const float*)d_in[2];
    const float* v_r = (const float*)d_in[3];
    const int* pos_u   = (const int*)d_in[4];
    const int* pos_v_l = (const int*)d_in[5];
    const int* pos_v_r = (const int*)d_in[6];
    const int* neg_v_l = (const int*)d_in[7];
    const int* neg_v_r = (const int*)d_in[8];

    const int batch = in_sizes[4];
    const int nb = (batch + WARPS_PER_BLOCK - 1) / WARPS_PER_BLOCK;

    skipgram_loss_kernel<<<2 * nb, BLOCK_THREADS>>>(
        u_l, u_r, v_l, v_r, pos_u, pos_v_l, pos_v_r, neg_v_l, neg_v_r,
        (float*)d_out, batch);
}